// round 6
// baseline (speedup 1.0000x reference)
#include <cuda_runtime.h>
#include <cstdint>

#define IN_DIM   1024
#define OUT_DIM  65536
#define BATCH    32
#define NPAIR    16                  // 32 batch rows as 16 f32x2 pairs
#define NC       2                   // columns per thread
#define THREADS  128
#define KSPLIT   4
#define KS       (IN_DIM / KSPLIT)   // 256 k per work item
#define UNROLL   4
#define NGROUPS  (KS / UNROLL)       // 64
#define COLS_CTA (THREADS * NC)      // 256
#define NCOLGRP  (OUT_DIM / COLS_CTA)       // 256
#define WORK_ITEMS (KSPLIT * NCOLGRP)       // 1024
#define GRID     608                 // ~4 CTAs/SM on 148-152 SMs

__device__ float g_partial[KSPLIT * BATCH * OUT_DIM];
__device__ int   g_work;
__device__ int   g_done[NCOLGRP];

__device__ __forceinline__ unsigned long long pack2(float lo, float hi) {
    unsigned long long r;
    asm("mov.b64 %0, {%1, %2};" : "=l"(r) : "f"(lo), "f"(hi));
    return r;
}
__device__ __forceinline__ void unpack2(unsigned long long v, float& lo, float& hi) {
    asm("mov.b64 {%0, %1}, %2;" : "=f"(lo), "=f"(hi) : "l"(v));
}
// d = a * b + d  (packed 2x fp32 FFMA2 — PTX-only)
__device__ __forceinline__ void ffma2(unsigned long long& d,
                                      unsigned long long a,
                                      unsigned long long b) {
    asm("fma.rn.f32x2 %0, %1, %2, %3;" : "=l"(d) : "l"(a), "l"(b), "l"(d));
}

__global__ void reset_kernel() {
    const int t = threadIdx.x;
    if (t < NCOLGRP) g_done[t] = 0;
    if (t == 0) g_work = GRID;
}

__global__ __launch_bounds__(THREADS, 4)
void sparse_linear_fused(const float* __restrict__ x,
                         const float* __restrict__ mask,
                         const float* __restrict__ w,
                         const float* __restrict__ bias,
                         float* __restrict__ out)
{
    __shared__ alignas(16) unsigned long long xs[KS][NPAIR];   // 32 KB
    __shared__ int s_flag;
    __shared__ int s_next;

    const int tid = threadIdx.x;
    int item = blockIdx.x;

    while (item < WORK_ITEMS) {
        const int cg      = item >> 2;       // column group
        const int split   = item & 3;        // k split
        const int kbase   = split * KS;
        const int colbase = cg * COLS_CTA;
        const int col0    = colbase + NC * tid;

        // ---- stage x slice for this split ----
        for (int idx = tid; idx < KS * NPAIR; idx += THREADS) {
            int k = idx / NPAIR, p = idx % NPAIR;
            xs[k][p] = pack2(x[(size_t)(2 * p)     * IN_DIM + kbase + k],
                             x[(size_t)(2 * p + 1) * IN_DIM + kbase + k]);
        }
        __syncthreads();

        // ---- main loop, register double-buffered ----
        unsigned long long acc[NPAIR][NC];
#pragma unroll
        for (int p = 0; p < NPAIR; p++)
#pragma unroll
            for (int c = 0; c < NC; c++) acc[p][c] = 0ULL;

        const float* wbase = w    + (size_t)kbase * OUT_DIM + col0;
        const float* mbase = mask + (size_t)kbase * OUT_DIM + col0;

        float2 wA[UNROLL], mA[UNROLL], wB[UNROLL], mB[UNROLL];

#define LOAD_GROUP(WB, MB, G)                                                   \
    {                                                                           \
        _Pragma("unroll")                                                       \
        for (int u = 0; u < UNROLL; u++) {                                      \
            const size_t off = (size_t)((G) * UNROLL + u) * OUT_DIM;            \
            (WB)[u] = *reinterpret_cast<const float2*>(wbase + off);            \
            (MB)[u] = *reinterpret_cast<const float2*>(mbase + off);            \
        }                                                                       \
    }

#define COMPUTE_GROUP(WB, MB, G)                                                \
    {                                                                           \
        _Pragma("unroll")                                                       \
        for (int u = 0; u < UNROLL; u++) {                                      \
            const float m0 = (WB)[u].x * (MB)[u].x;                             \
            const float m1 = (WB)[u].y * (MB)[u].y;                             \
            const unsigned long long bb0 = pack2(m0, m0);                       \
            const unsigned long long bb1 = pack2(m1, m1);                       \
            const ulonglong2* xr =                                              \
                reinterpret_cast<const ulonglong2*>(&xs[(G) * UNROLL + u][0]);  \
            _Pragma("unroll")                                                   \
            for (int q = 0; q < NPAIR / 2; q++) {                               \
                const ulonglong2 xv = xr[q];                                    \
                ffma2(acc[2 * q][0],     xv.x, bb0);                            \
                ffma2(acc[2 * q][1],     xv.x, bb1);                            \
                ffma2(acc[2 * q + 1][0], xv.y, bb0);                            \
                ffma2(acc[2 * q + 1][1], xv.y, bb1);                            \
            }                                                                   \
        }                                                                       \
    }

        LOAD_GROUP(wA, mA, 0);
#pragma unroll 1
        for (int g = 0; g < NGROUPS; g += 2) {
            LOAD_GROUP(wB, mB, g + 1);
            COMPUTE_GROUP(wA, mA, g);
            if (g + 2 < NGROUPS) LOAD_GROUP(wA, mA, g + 2);
            COMPUTE_GROUP(wB, mB, g + 1);
        }
#undef LOAD_GROUP
#undef COMPUTE_GROUP

        // ---- write partials ----
        float* part = g_partial + (size_t)split * BATCH * OUT_DIM;
#pragma unroll
        for (int p = 0; p < NPAIR; p++) {
            float a0lo, a0hi, a1lo, a1hi;
            unpack2(acc[p][0], a0lo, a0hi);
            unpack2(acc[p][1], a1lo, a1hi);
            *reinterpret_cast<float2*>(part + (size_t)(2 * p)     * OUT_DIM + col0) =
                make_float2(a0lo, a1lo);
            *reinterpret_cast<float2*>(part + (size_t)(2 * p + 1) * OUT_DIM + col0) =
                make_float2(a0hi, a1hi);
        }

        // ---- arrival protocol (FIXED) ----
        // 1. each thread orders its own partial stores at gpu scope
        __threadfence();
        // 2. make sure ALL threads of this CTA have issued+fenced their stores
        __syncthreads();
        // 3. only now may tid0 announce this split's completion
        if (tid == 0) {
            const int old = atomicAdd(&g_done[cg], 1);
            s_flag = (old == KSPLIT - 1);
            s_next = atomicAdd(&g_work, 1);     // fetch next work item
        }
        __syncthreads();

        if (s_flag) {
            // acquire side: order the flag observation before the partial loads
            __threadfence();
            const int rc0 = colbase + 2 * tid;
            const float2 b2 = *reinterpret_cast<const float2*>(bias + rc0);
#pragma unroll 4
            for (int b = 0; b < BATCH; b++) {
                const size_t off = (size_t)b * OUT_DIM + rc0;
                float2 s = __ldcg(reinterpret_cast<const float2*>(g_partial + off));
#pragma unroll
                for (int sp = 1; sp < KSPLIT; sp++) {
                    const float2 v = __ldcg(reinterpret_cast<const float2*>(
                        g_partial + (size_t)sp * BATCH * OUT_DIM + off));
                    s.x += v.x; s.y += v.y;
                }
                s.x += b2.x; s.y += b2.y;
                *reinterpret_cast<float2*>(out + off) = s;
            }
        }
        __syncthreads();   // protect s_flag/s_next/xs before next iteration
        item = s_next;
    }
}

extern "C" void kernel_launch(void* const* d_in, const int* in_sizes, int n_in,
                              void* d_out, int out_size) {
    const float* x    = (const float*)d_in[0];
    const float* mask = (const float*)d_in[1];
    const float* w    = (const float*)d_in[2];
    const float* bias = (const float*)d_in[3];
    float* out = (float*)d_out;

    reset_kernel<<<1, 256>>>();
    sparse_linear_fused<<<GRID, THREADS>>>(x, mask, w, bias, out);
}